// round 3
// baseline (speedup 1.0000x reference)
#include <cuda_runtime.h>
#include <math.h>

// Problem constants
#define BB   2
#define TT   8192
#define HH   16
#define NBB  32
#define DD   1024
#define DHH  128
#define CHN  (HH*NBB)          // 512
#define MM   (BB*TT)           // 16384

// Scan chunking
#define SCAN_L 32
#define SCAN_C (TT/SCAN_L)     // 256

// Output layout: theta_hat [B,T,H,NB], d [B,T,H,NB], K_star [H,NB]
#define OFF_D  ((size_t)BB*TT*CHN)     // 8388608
#define OFF_K  (2*OFF_D)               // 16777216

// Scratch (static device allocations; no cudaMalloc allowed)
__device__ __align__(16) float g_hid[(size_t)MM*DHH];       // 8.4 MB
__device__ __align__(16) float g_nu [(size_t)MM*CHN];       // 33.5 MB
__device__ __align__(16) float g_K[CHN];
__device__ __align__(16) float g_alpha[CHN];
__device__ __align__(16) float g_alphaL[CHN];
__device__ __align__(16) float g_Bmat[(size_t)BB*SCAN_C*CHN];
__device__ __align__(16) float g_D0 [(size_t)BB*SCAN_C*CHN];

typedef unsigned long long ull;

// ---------------------------------------------------------------------------
// packed fp32x2 helpers (sm_103a FFMA2)
__device__ __forceinline__ void ffma2(ull& d, ull a, ull b) {
    asm("fma.rn.f32x2 %0, %1, %2, %0;" : "+l"(d) : "l"(a), "l"(b));
}
__device__ __forceinline__ ull pack2(float x) {
    ull r; asm("mov.b64 %0, {%1, %1};" : "=l"(r) : "f"(x)); return r;
}
__device__ __forceinline__ void unpack2(ull v, float& lo, float& hi) {
    asm("mov.b64 {%0, %1}, %2;" : "=f"(lo), "=f"(hi) : "l"(v));
}

// ---------------------------------------------------------------------------
// K* = (P+Q)/(P+Q+R),  P = (-Q + sqrt(Q^2+4QR))/2
__global__ void kstar_kernel(const float* __restrict__ lQ,
                             const float* __restrict__ lR,
                             float* __restrict__ out) {
    int c = threadIdx.x;  // 512
    float Q = expf(lQ[c]);
    float R = expf(lR[c]);
    float P_post = 0.5f * (-Q + sqrtf(Q * Q + 4.0f * Q * R));
    float P_pred = P_post + Q;
    float Kc = P_pred / (P_pred + R);
    float a = 1.0f - Kc;
    g_K[c] = Kc;
    g_alpha[c] = a;
    g_alphaL[c] = powf(a, (float)SCAN_L);
    out[OFF_K + c] = Kc;
}

// ---------------------------------------------------------------------------
// FFMA2 tiled fp32 GEMM with double-buffered smem.
// BM=BN=128, BK=16, 256 threads, 8x8 microtile per thread.
// EPI==0: C = gelu(A@W + b)           -> g_hid   (A = content_emb, K=1024, N=128)
// EPI==1: nu = wrap(pi*tanh(hid@W+b) - theta) -> g_nu  (A = g_hid, K=128, N=512)
#define BM 128
#define BN 128
#define BK 16

__device__ __forceinline__ float gelu_exact(float x) {
    return 0.5f * x * (1.0f + erff(x * 0.70710678118654752f));
}

template<int KDIM, int NSTRIDE, int EPI>
__global__ __launch_bounds__(256)
void gemm_ffma2(const float* __restrict__ Ain,
                const float* __restrict__ Bw,
                const float* __restrict__ bias,
                const float* __restrict__ theta) {
    __shared__ __align__(16) float As[2][BK][BM];
    __shared__ __align__(16) float Bs[2][BK][BN];
    const int bm = blockIdx.x;
    const int bn = blockIdx.y;
    const int tid = threadIdx.x;
    const int ty = tid >> 4, tx = tid & 15;

    const float* A = (EPI == 0) ? Ain : (const float*)g_hid;
    const float* Ablk = A + (size_t)bm * BM * KDIM;
    const float* Bblk = Bw + bn * BN;

    ull acc[4][8];
    #pragma unroll
    for (int p = 0; p < 4; p++)
        #pragma unroll
        for (int j = 0; j < 8; j++) acc[p][j] = 0ULL;

    float4 ra[2], rb[2];

    // --- global load of tile (k0) into registers ---
    #define LOADG(k0)                                                          \
        {                                                                      \
            _Pragma("unroll")                                                  \
            for (int it = 0; it < 2; it++) {                                   \
                int slot = it * 256 + tid;                                     \
                ra[it] = *(const float4*)(Ablk + (size_t)(slot >> 2) * KDIM +  \
                                          (k0) + (slot & 3) * 4);              \
                rb[it] = *(const float4*)(Bblk +                               \
                          (size_t)((k0) + (slot >> 5)) * NSTRIDE +             \
                          (slot & 31) * 4);                                    \
            }                                                                  \
        }
    // --- store staged registers to smem buffer ---
    #define STOS(buf)                                                          \
        {                                                                      \
            _Pragma("unroll")                                                  \
            for (int it = 0; it < 2; it++) {                                   \
                int slot = it * 256 + tid;                                     \
                int row = slot >> 2, k4 = (slot & 3) * 4;                      \
                As[buf][k4 + 0][row] = ra[it].x;                               \
                As[buf][k4 + 1][row] = ra[it].y;                               \
                As[buf][k4 + 2][row] = ra[it].z;                               \
                As[buf][k4 + 3][row] = ra[it].w;                               \
                *(float4*)&Bs[buf][slot >> 5][(slot & 31) * 4] = rb[it];       \
            }                                                                  \
        }

    LOADG(0);
    STOS(0);
    __syncthreads();

    const int NT = KDIM / BK;
    int cur = 0;
    for (int t = 0; t < NT; t++) {
        if (t + 1 < NT) LOADG((t + 1) * BK);
        #pragma unroll
        for (int k = 0; k < BK; k++) {
            ulonglong2 a0 = *(const ulonglong2*)&As[cur][k][ty * 4];
            ulonglong2 a1 = *(const ulonglong2*)&As[cur][k][64 + ty * 4];
            float4 b0 = *(const float4*)&Bs[cur][k][tx * 4];
            float4 b1 = *(const float4*)&Bs[cur][k][64 + tx * 4];
            ull ap[4] = {a0.x, a0.y, a1.x, a1.y};
            ull bb[8] = {pack2(b0.x), pack2(b0.y), pack2(b0.z), pack2(b0.w),
                         pack2(b1.x), pack2(b1.y), pack2(b1.z), pack2(b1.w)};
            #pragma unroll
            for (int p = 0; p < 4; p++)
                #pragma unroll
                for (int j = 0; j < 8; j++)
                    ffma2(acc[p][j], ap[p], bb[j]);
        }
        if (t + 1 < NT) STOS(cur ^ 1);
        __syncthreads();
        cur ^= 1;
    }

    // --- epilogue ---
    const float PI_F     = 3.14159265358979323846f;
    const float INV_2PI  = 0.15915494309189533577f;
    const float TWO_PI   = 6.28318530717958647693f;
    #pragma unroll
    for (int p = 0; p < 4; p++) {
        int rl = (p >> 1) * 64 + ty * 4 + (p & 1) * 2;
        #pragma unroll
        for (int lane = 0; lane < 2; lane++) {
            int row = bm * BM + rl + lane;
            float v[8];
            #pragma unroll
            for (int j = 0; j < 8; j++) {
                float lo, hi;
                unpack2(acc[p][j], lo, hi);
                v[j] = lane ? hi : lo;
            }
            #pragma unroll
            for (int half = 0; half < 2; half++) {
                int coll = half * 64 + tx * 4;          // local col
                if (EPI == 0) {
                    float4 o;
                    float* po = (float*)&o;
                    #pragma unroll
                    for (int j = 0; j < 4; j++) {
                        float x = v[half * 4 + j] + bias[coll + j];
                        po[j] = gelu_exact(x);
                    }
                    *(float4*)&g_hid[(size_t)row * DHH + coll] = o;
                } else {
                    int col = bn * BN + coll;
                    float4 th = *(const float4*)&theta[(size_t)row * CHN + col];
                    const float* pth = (const float*)&th;
                    float4 o;
                    float* po = (float*)&o;
                    #pragma unroll
                    for (int j = 0; j < 4; j++) {
                        float zr = v[half * 4 + j] + bias[col + j];
                        float z = PI_F * tanhf(zr);
                        float dif = z - pth[j];
                        po[j] = dif - TWO_PI * rintf(dif * INV_2PI);
                    }
                    *(float4*)&g_nu[(size_t)row * CHN + col] = o;
                }
            }
        }
    }
    #undef LOADG
    #undef STOS
}

// ---------------------------------------------------------------------------
// Scan pass 1: per-(b,chunk,channel4) compute B_c = sum_{i<L} alpha^{L-1-i} K nu_i
__global__ void scan_pass1() {
    int t = threadIdx.x;        // 128 threads, 4 channels each
    int c = blockIdx.x;         // chunk (256)
    int b = blockIdx.y;
    const float4 a4 = ((const float4*)g_alpha)[t];
    const float4 K4 = ((const float4*)g_K)[t];
    const float4* nu4 = (const float4*)g_nu +
                        ((size_t)b * TT + (size_t)c * SCAN_L) * (CHN / 4) + t;
    float4 s = {0.f, 0.f, 0.f, 0.f};
    #pragma unroll 8
    for (int i = 0; i < SCAN_L; i++) {
        float4 v = nu4[(size_t)i * (CHN / 4)];
        s.x = fmaf(a4.x, s.x, K4.x * v.x);
        s.y = fmaf(a4.y, s.y, K4.y * v.y);
        s.z = fmaf(a4.z, s.z, K4.z * v.z);
        s.w = fmaf(a4.w, s.w, K4.w * v.w);
    }
    ((float4*)g_Bmat)[((size_t)b * SCAN_C + c) * (CHN / 4) + t] = s;
}

// Scan pass 2: carry across chunks. D0[c] = carry before chunk c.
__global__ void scan_pass2() {
    int t = threadIdx.x;        // 128
    int b = blockIdx.x;         // 2
    const float4 aL = ((const float4*)g_alphaL)[t];
    float4 carry = {0.f, 0.f, 0.f, 0.f};
    #pragma unroll 4
    for (int c = 0; c < SCAN_C; c++) {
        size_t idx = ((size_t)b * SCAN_C + c) * (CHN / 4) + t;
        ((float4*)g_D0)[idx] = carry;
        float4 Bv = ((const float4*)g_Bmat)[idx];
        carry.x = fmaf(aL.x, carry.x, Bv.x);
        carry.y = fmaf(aL.y, carry.y, Bv.y);
        carry.z = fmaf(aL.z, carry.z, Bv.z);
        carry.w = fmaf(aL.w, carry.w, Bv.w);
    }
}

// Scan pass 3: replay chunk with correct carry, write d and theta_hat
__global__ void scan_pass3(const float* __restrict__ theta,
                           float* __restrict__ out) {
    int t = threadIdx.x;
    int c = blockIdx.x;
    int b = blockIdx.y;
    const float4 a4 = ((const float4*)g_alpha)[t];
    const float4 K4 = ((const float4*)g_K)[t];
    float4 d = ((const float4*)g_D0)[((size_t)b * SCAN_C + c) * (CHN / 4) + t];
    size_t base = ((size_t)b * TT + (size_t)c * SCAN_L) * (CHN / 4) + t;
    const float4* nu4 = (const float4*)g_nu + base;
    const float4* th4 = (const float4*)theta + base;
    float4* outh = (float4*)out + base;
    float4* outd = (float4*)(out + OFF_D) + base;
    #pragma unroll 4
    for (int i = 0; i < SCAN_L; i++) {
        size_t idx = (size_t)i * (CHN / 4);
        float4 v = nu4[idx];
        float4 th = th4[idx];
        d.x = fmaf(a4.x, d.x, K4.x * v.x);
        d.y = fmaf(a4.y, d.y, K4.y * v.y);
        d.z = fmaf(a4.z, d.z, K4.z * v.z);
        d.w = fmaf(a4.w, d.w, K4.w * v.w);
        outd[idx] = d;
        float4 o = {th.x + d.x, th.y + d.y, th.z + d.z, th.w + d.w};
        outh[idx] = o;
    }
}

// ---------------------------------------------------------------------------
extern "C" void kernel_launch(void* const* d_in, const int* in_sizes, int n_in,
                              void* d_out, int out_size) {
    const float* theta   = (const float*)d_in[0];  // (B,T,H,NB)
    const float* content = (const float*)d_in[1];  // (B,T,D)
    const float* W1      = (const float*)d_in[2];  // (D,DH)
    const float* b1      = (const float*)d_in[3];  // (DH,)
    const float* W2      = (const float*)d_in[4];  // (DH,H*NB)
    const float* b2      = (const float*)d_in[5];  // (H*NB,)
    const float* lQ      = (const float*)d_in[6];  // (H,NB)
    const float* lR      = (const float*)d_in[7];  // (H,NB)
    float* out = (float*)d_out;

    kstar_kernel<<<1, CHN>>>(lQ, lR, out);
    gemm_ffma2<DD, DHH, 0><<<dim3(MM / BM, 1), 256>>>(content, W1, b1, nullptr);
    gemm_ffma2<DHH, CHN, 1><<<dim3(MM / BM, CHN / BN), 256>>>(nullptr, W2, b2, theta);
    scan_pass1<<<dim3(SCAN_C, BB), 128>>>();
    scan_pass2<<<BB, 128>>>();
    scan_pass3<<<dim3(SCAN_C, BB), 128>>>(theta, out);
}

// round 4
// speedup vs baseline: 1.0450x; 1.0450x over previous
#include <cuda_runtime.h>
#include <math.h>

// Problem constants
#define BB   2
#define TT   8192
#define HH   16
#define NBB  32
#define DD   1024
#define DHH  128
#define CHN  (HH*NBB)          // 512
#define MM   (BB*TT)           // 16384

// Scan chunking
#define SCAN_L 32
#define SCAN_C (TT/SCAN_L)     // 256

// Output layout: theta_hat [B,T,H,NB], d [B,T,H,NB], K_star [H,NB]
#define OFF_D  ((size_t)BB*TT*CHN)     // 8388608
#define OFF_K  (2*OFF_D)               // 16777216

// Scratch (static device allocations; no cudaMalloc allowed)
__device__ __align__(16) float g_hid[(size_t)MM*DHH];       // 8.4 MB
__device__ __align__(16) float g_nu [(size_t)MM*CHN];       // 33.5 MB
__device__ __align__(16) float g_K[CHN];
__device__ __align__(16) float g_alpha[CHN];
__device__ __align__(16) float g_alphaL[CHN];
__device__ __align__(16) float g_Bmat[(size_t)BB*SCAN_C*CHN];
__device__ __align__(16) float g_D0 [(size_t)BB*SCAN_C*CHN];

typedef unsigned long long ull;

// ---------------------------------------------------------------------------
// packed fp32x2 helpers (sm_103a FFMA2)
__device__ __forceinline__ void ffma2(ull& d, ull a, ull b) {
    asm("fma.rn.f32x2 %0, %1, %2, %0;" : "+l"(d) : "l"(a), "l"(b));
}
__device__ __forceinline__ ull pack2(float x) {
    ull r; asm("mov.b64 %0, {%1, %1};" : "=l"(r) : "f"(x)); return r;
}
__device__ __forceinline__ void unpack2(ull v, float& lo, float& hi) {
    asm("mov.b64 {%0, %1}, %2;" : "=f"(lo), "=f"(hi) : "l"(v));
}

// ---------------------------------------------------------------------------
// K* = (P+Q)/(P+Q+R),  P = (-Q + sqrt(Q^2+4QR))/2
__global__ void kstar_kernel(const float* __restrict__ lQ,
                             const float* __restrict__ lR,
                             float* __restrict__ out) {
    int c = threadIdx.x;  // 512
    float Q = expf(lQ[c]);
    float R = expf(lR[c]);
    float P_post = 0.5f * (-Q + sqrtf(Q * Q + 4.0f * Q * R));
    float P_pred = P_post + Q;
    float Kc = P_pred / (P_pred + R);
    float a = 1.0f - Kc;
    g_K[c] = Kc;
    g_alpha[c] = a;
    g_alphaL[c] = powf(a, (float)SCAN_L);
    out[OFF_K + c] = Kc;
}

// ---------------------------------------------------------------------------
// FFMA2 tiled fp32 GEMM with double-buffered smem.
// BM=BN=128, BK=16, 256 threads, 8x8 microtile per thread.
// EPI==0: C = gelu(A@W + b)           -> g_hid   (A = content_emb, K=1024, N=128)
// EPI==1: nu = wrap(pi*tanh(hid@W+b) - theta) -> g_nu  (A = g_hid, K=128, N=512)
#define BM 128
#define BN 128
#define BK 16

__device__ __forceinline__ float gelu_exact(float x) {
    return 0.5f * x * (1.0f + erff(x * 0.70710678118654752f));
}

template<int KDIM, int NSTRIDE, int EPI>
__global__ __launch_bounds__(256)
void gemm_ffma2(const float* __restrict__ Ain,
                const float* __restrict__ Bw,
                const float* __restrict__ bias,
                const float* __restrict__ theta) {
    __shared__ __align__(16) float As[2][BK][BM];
    __shared__ __align__(16) float Bs[2][BK][BN];
    const int bm = blockIdx.x;
    const int bn = blockIdx.y;
    const int tid = threadIdx.x;
    const int ty = tid >> 4, tx = tid & 15;

    const float* A = (EPI == 0) ? Ain : (const float*)g_hid;
    const float* Ablk = A + (size_t)bm * BM * KDIM;
    const float* Bblk = Bw + bn * BN;

    ull acc[4][8];
    #pragma unroll
    for (int p = 0; p < 4; p++)
        #pragma unroll
        for (int j = 0; j < 8; j++) acc[p][j] = 0ULL;

    float4 ra[2], rb[2];

    // --- global load of tile (k0) into registers ---
    #define LOADG(k0)                                                          \
        {                                                                      \
            _Pragma("unroll")                                                  \
            for (int it = 0; it < 2; it++) {                                   \
                int slot = it * 256 + tid;                                     \
                ra[it] = *(const float4*)(Ablk + (size_t)(slot >> 2) * KDIM +  \
                                          (k0) + (slot & 3) * 4);              \
                rb[it] = *(const float4*)(Bblk +                               \
                          (size_t)((k0) + (slot >> 5)) * NSTRIDE +             \
                          (slot & 31) * 4);                                    \
            }                                                                  \
        }
    // --- store staged registers to smem buffer ---
    #define STOS(buf)                                                          \
        {                                                                      \
            _Pragma("unroll")                                                  \
            for (int it = 0; it < 2; it++) {                                   \
                int slot = it * 256 + tid;                                     \
                int row = slot >> 2, k4 = (slot & 3) * 4;                      \
                As[buf][k4 + 0][row] = ra[it].x;                               \
                As[buf][k4 + 1][row] = ra[it].y;                               \
                As[buf][k4 + 2][row] = ra[it].z;                               \
                As[buf][k4 + 3][row] = ra[it].w;                               \
                *(float4*)&Bs[buf][slot >> 5][(slot & 31) * 4] = rb[it];       \
            }                                                                  \
        }

    LOADG(0);
    STOS(0);
    __syncthreads();

    const int NT = KDIM / BK;
    int cur = 0;
    for (int t = 0; t < NT; t++) {
        if (t + 1 < NT) LOADG((t + 1) * BK);
        #pragma unroll
        for (int k = 0; k < BK; k++) {
            ulonglong2 a0 = *(const ulonglong2*)&As[cur][k][ty * 4];
            ulonglong2 a1 = *(const ulonglong2*)&As[cur][k][64 + ty * 4];
            float4 b0 = *(const float4*)&Bs[cur][k][tx * 4];
            float4 b1 = *(const float4*)&Bs[cur][k][64 + tx * 4];
            ull ap[4] = {a0.x, a0.y, a1.x, a1.y};
            ull bb[8] = {pack2(b0.x), pack2(b0.y), pack2(b0.z), pack2(b0.w),
                         pack2(b1.x), pack2(b1.y), pack2(b1.z), pack2(b1.w)};
            #pragma unroll
            for (int p = 0; p < 4; p++)
                #pragma unroll
                for (int j = 0; j < 8; j++)
                    ffma2(acc[p][j], ap[p], bb[j]);
        }
        if (t + 1 < NT) STOS(cur ^ 1);
        __syncthreads();
        cur ^= 1;
    }

    // --- epilogue ---
    const float PI_F     = 3.14159265358979323846f;
    const float INV_2PI  = 0.15915494309189533577f;
    const float TWO_PI   = 6.28318530717958647693f;
    #pragma unroll
    for (int p = 0; p < 4; p++) {
        int rl = (p >> 1) * 64 + ty * 4 + (p & 1) * 2;
        #pragma unroll
        for (int lane = 0; lane < 2; lane++) {
            int row = bm * BM + rl + lane;
            float v[8];
            #pragma unroll
            for (int j = 0; j < 8; j++) {
                float lo, hi;
                unpack2(acc[p][j], lo, hi);
                v[j] = lane ? hi : lo;
            }
            #pragma unroll
            for (int half = 0; half < 2; half++) {
                int coll = half * 64 + tx * 4;          // local col
                if (EPI == 0) {
                    float4 o;
                    float* po = (float*)&o;
                    #pragma unroll
                    for (int j = 0; j < 4; j++) {
                        float x = v[half * 4 + j] + bias[coll + j];
                        po[j] = gelu_exact(x);
                    }
                    *(float4*)&g_hid[(size_t)row * DHH + coll] = o;
                } else {
                    int col = bn * BN + coll;
                    float4 th = *(const float4*)&theta[(size_t)row * CHN + col];
                    const float* pth = (const float*)&th;
                    float4 o;
                    float* po = (float*)&o;
                    #pragma unroll
                    for (int j = 0; j < 4; j++) {
                        float zr = v[half * 4 + j] + bias[col + j];
                        float z = PI_F * tanhf(zr);
                        float dif = z - pth[j];
                        po[j] = dif - TWO_PI * rintf(dif * INV_2PI);
                    }
                    *(float4*)&g_nu[(size_t)row * CHN + col] = o;
                }
            }
        }
    }
    #undef LOADG
    #undef STOS
}

// ---------------------------------------------------------------------------
// Scan pass 1: per-(b,chunk,channel4) compute B_c = sum_{i<L} alpha^{L-1-i} K nu_i
__global__ void scan_pass1() {
    int t = threadIdx.x;        // 128 threads, 4 channels each
    int c = blockIdx.x;         // chunk (256)
    int b = blockIdx.y;
    const float4 a4 = ((const float4*)g_alpha)[t];
    const float4 K4 = ((const float4*)g_K)[t];
    const float4* nu4 = (const float4*)g_nu +
                        ((size_t)b * TT + (size_t)c * SCAN_L) * (CHN / 4) + t;
    float4 s = {0.f, 0.f, 0.f, 0.f};
    #pragma unroll 8
    for (int i = 0; i < SCAN_L; i++) {
        float4 v = nu4[(size_t)i * (CHN / 4)];
        s.x = fmaf(a4.x, s.x, K4.x * v.x);
        s.y = fmaf(a4.y, s.y, K4.y * v.y);
        s.z = fmaf(a4.z, s.z, K4.z * v.z);
        s.w = fmaf(a4.w, s.w, K4.w * v.w);
    }
    ((float4*)g_Bmat)[((size_t)b * SCAN_C + c) * (CHN / 4) + t] = s;
}

// Scan pass 2: carry across chunks. D0[c] = carry before chunk c.
__global__ void scan_pass2() {
    int t = threadIdx.x;        // 128
    int b = blockIdx.x;         // 2
    const float4 aL = ((const float4*)g_alphaL)[t];
    float4 carry = {0.f, 0.f, 0.f, 0.f};
    #pragma unroll 4
    for (int c = 0; c < SCAN_C; c++) {
        size_t idx = ((size_t)b * SCAN_C + c) * (CHN / 4) + t;
        ((float4*)g_D0)[idx] = carry;
        float4 Bv = ((const float4*)g_Bmat)[idx];
        carry.x = fmaf(aL.x, carry.x, Bv.x);
        carry.y = fmaf(aL.y, carry.y, Bv.y);
        carry.z = fmaf(aL.z, carry.z, Bv.z);
        carry.w = fmaf(aL.w, carry.w, Bv.w);
    }
}

// Scan pass 3: replay chunk with correct carry, write d and theta_hat
__global__ void scan_pass3(const float* __restrict__ theta,
                           float* __restrict__ out) {
    int t = threadIdx.x;
    int c = blockIdx.x;
    int b = blockIdx.y;
    const float4 a4 = ((const float4*)g_alpha)[t];
    const float4 K4 = ((const float4*)g_K)[t];
    float4 d = ((const float4*)g_D0)[((size_t)b * SCAN_C + c) * (CHN / 4) + t];
    size_t base = ((size_t)b * TT + (size_t)c * SCAN_L) * (CHN / 4) + t;
    const float4* nu4 = (const float4*)g_nu + base;
    const float4* th4 = (const float4*)theta + base;
    float4* outh = (float4*)out + base;
    float4* outd = (float4*)(out + OFF_D) + base;
    #pragma unroll 4
    for (int i = 0; i < SCAN_L; i++) {
        size_t idx = (size_t)i * (CHN / 4);
        float4 v = nu4[idx];
        float4 th = th4[idx];
        d.x = fmaf(a4.x, d.x, K4.x * v.x);
        d.y = fmaf(a4.y, d.y, K4.y * v.y);
        d.z = fmaf(a4.z, d.z, K4.z * v.z);
        d.w = fmaf(a4.w, d.w, K4.w * v.w);
        outd[idx] = d;
        float4 o = {th.x + d.x, th.y + d.y, th.z + d.z, th.w + d.w};
        outh[idx] = o;
    }
}

// ---------------------------------------------------------------------------
extern "C" void kernel_launch(void* const* d_in, const int* in_sizes, int n_in,
                              void* d_out, int out_size) {
    const float* theta   = (const float*)d_in[0];  // (B,T,H,NB)
    const float* content = (const float*)d_in[1];  // (B,T,D)
    const float* W1      = (const float*)d_in[2];  // (D,DH)
    const float* b1      = (const float*)d_in[3];  // (DH,)
    const float* W2      = (const float*)d_in[4];  // (DH,H*NB)
    const float* b2      = (const float*)d_in[5];  // (H*NB,)
    const float* lQ      = (const float*)d_in[6];  // (H,NB)
    const float* lR      = (const float*)d_in[7];  // (H,NB)
    float* out = (float*)d_out;

    kstar_kernel<<<1, CHN>>>(lQ, lR, out);
    gemm_ffma2<DD, DHH, 0><<<dim3(MM / BM, 1), 256>>>(content, W1, b1, nullptr);
    gemm_ffma2<DHH, CHN, 1><<<dim3(MM / BM, CHN / BN), 256>>>(nullptr, W2, b2, theta);
    scan_pass1<<<dim3(SCAN_C, BB), 128>>>();
    scan_pass2<<<BB, 128>>>();
    scan_pass3<<<dim3(SCAN_C, BB), 128>>>(theta, out);
}